// round 7
// baseline (speedup 1.0000x reference)
#include <cuda_runtime.h>

// Problem: fused confusion-matrix reduction.
//   y_pred, y_true: [16, 3, 512, 512] f32 -> out [16, 3, 4] = [tp, tn, fp, fn]
// tp = sum(p*t); fp = sum(p) - tp; fn = sum(t) - tp; tn = N - sum(p) - sum(t) + tp.
// Pure HBM-bound streaming reduction over 100.66 MB.

#define SLICES 48                       // B*C
#define N_PER_SLICE (512 * 512)         // 262144 elements per slice
#define BLOCKS_PER_SLICE 32
#define THREADS 256
#define ELEMS_PER_BLOCK (N_PER_SLICE / BLOCKS_PER_SLICE)          // 8192
#define VECS_PER_BLOCK (ELEMS_PER_BLOCK / 4)                      // 2048 float4
#define VECS_PER_THREAD (VECS_PER_BLOCK / THREADS)                // 8

// Per-block partials: [slice][block][3] = {sum_p, sum_t, sum_pt}.
// Every slot is overwritten each launch -> deterministic, graph-replay safe.
__device__ float g_part[SLICES * BLOCKS_PER_SLICE * 3];

__global__ __launch_bounds__(THREADS)
void cm_reduce_kernel(const float4* __restrict__ p4, const float4* __restrict__ t4) {
    const int blk = blockIdx.x;                         // 0 .. 1535
    const long base = (long)blk * VECS_PER_BLOCK + threadIdx.x;

    float sp = 0.0f, st = 0.0f, spt = 0.0f;

#pragma unroll
    for (int i = 0; i < VECS_PER_THREAD; i++) {
        const float4 pv = __ldg(&p4[base + (long)i * THREADS]);
        const float4 tv = __ldg(&t4[base + (long)i * THREADS]);
        sp  += (pv.x + pv.y) + (pv.z + pv.w);
        st  += (tv.x + tv.y) + (tv.z + tv.w);
        spt += pv.x * tv.x + pv.y * tv.y + pv.z * tv.z + pv.w * tv.w;
    }

    // Warp-level tree reduction.
#pragma unroll
    for (int off = 16; off > 0; off >>= 1) {
        sp  += __shfl_down_sync(0xFFFFFFFFu, sp,  off);
        st  += __shfl_down_sync(0xFFFFFFFFu, st,  off);
        spt += __shfl_down_sync(0xFFFFFFFFu, spt, off);
    }

    __shared__ float sm[3][THREADS / 32];
    const int wid = threadIdx.x >> 5;
    const int lid = threadIdx.x & 31;
    if (lid == 0) {
        sm[0][wid] = sp;
        sm[1][wid] = st;
        sm[2][wid] = spt;
    }
    __syncthreads();

    if (threadIdx.x == 0) {
        float a = 0.0f, b = 0.0f, c = 0.0f;
#pragma unroll
        for (int w = 0; w < THREADS / 32; w++) {
            a += sm[0][w];
            b += sm[1][w];
            c += sm[2][w];
        }
        g_part[blk * 3 + 0] = a;
        g_part[blk * 3 + 1] = b;
        g_part[blk * 3 + 2] = c;
    }
}

__global__ void cm_finalize_kernel(float* __restrict__ out) {
    const int s = threadIdx.x;
    if (s >= SLICES) return;

    double sp = 0.0, st = 0.0, spt = 0.0;
#pragma unroll
    for (int b = 0; b < BLOCKS_PER_SLICE; b++) {
        const int idx = (s * BLOCKS_PER_SLICE + b) * 3;
        sp  += (double)g_part[idx + 0];
        st  += (double)g_part[idx + 1];
        spt += (double)g_part[idx + 2];
    }

    const double n = (double)N_PER_SLICE;
    // Output layout per slice: [tp, tn, fp, fn]
    out[s * 4 + 0] = (float)spt;                  // tp
    out[s * 4 + 1] = (float)(n - sp - st + spt);  // tn
    out[s * 4 + 2] = (float)(sp - spt);           // fp
    out[s * 4 + 3] = (float)(st - spt);           // fn
}

extern "C" void kernel_launch(void* const* d_in, const int* in_sizes, int n_in,
                              void* d_out, int out_size) {
    const float4* p4 = (const float4*)d_in[0];   // y_pred
    const float4* t4 = (const float4*)d_in[1];   // y_true
    float* out = (float*)d_out;

    cm_reduce_kernel<<<SLICES * BLOCKS_PER_SLICE, THREADS>>>(p4, t4);
    cm_finalize_kernel<<<1, 64>>>(out);
}